// round 1
// baseline (speedup 1.0000x reference)
#include <cuda_runtime.h>

#define TT 512
#define DD 256
#define LL 256
#define HH 512
#define ZDIM 1024
#define GPD 32   // CTAs per LSTM direction

// ---------------- device scratch (no allocations allowed) ----------------
__device__ __align__(16) float g_xw_a[TT * ZDIM];
__device__ __align__(16) float g_xw_b[TT * ZDIM];
__device__ __align__(16) float g_Ut[4][ZDIM * LL];   // transposed U: [col][k]
__device__ __align__(16) float g_rf1[TT * LL];
__device__ __align__(16) float g_rb1[TT * LL];
__device__ __align__(16) float g_rf2[TT * LL];
__device__ __align__(16) float g_rb2[TT * LL];
__device__ __align__(16) float g_v[TT * 2 * LL];
__device__ __align__(16) float g_hcat[TT * 2 * LL];
__device__ __align__(16) float g_headf[TT * HH];
__device__ __align__(16) float g_modf[TT * HH];
__device__ __align__(16) float g_hbuf[2][2][LL];     // [dir][pingpong][unit]
__device__ unsigned g_cnt[2];
__device__ volatile unsigned g_gen[2];

// ---------------- fast activations (rel err ~1e-6) ----------------
__device__ __forceinline__ float fsig(float x) {
    float e = __expf(-x);
    return __fdividef(1.f, 1.f + e);
}
__device__ __forceinline__ float ftanh(float x) {
    float e = __expf(2.f * x);
    return 1.f - __fdividef(2.f, e + 1.f);
}

// ---------------- U transpose: [256,1024] -> [1024,256] x4 ----------------
__global__ void transposeU_kernel(const float* __restrict__ u0, const float* __restrict__ u1,
                                  const float* __restrict__ u2, const float* __restrict__ u3) {
    __shared__ float tile[32][33];
    const float* src = (blockIdx.z == 0) ? u0 : (blockIdx.z == 1) ? u1 : (blockIdx.z == 2) ? u2 : u3;
    float* dst = g_Ut[blockIdx.z];
    int j  = blockIdx.x * 32 + threadIdx.x;   // column in U (0..1023)
    int k0 = blockIdx.y * 32;                 // row chunk (0..255)
#pragma unroll
    for (int r = 0; r < 32; r += 8)
        tile[threadIdx.y + r][threadIdx.x] = src[(k0 + threadIdx.y + r) * ZDIM + j];
    __syncthreads();
    int k  = k0 + threadIdx.x;
    int jo = blockIdx.x * 32;
#pragma unroll
    for (int r = 0; r < 32; r += 8)
        dst[(jo + threadIdx.y + r) * LL + k] = tile[threadIdx.x][threadIdx.y + r];
}

// ---------------- generic fp32 tiled GEMM: C = A[MxK] @ B[KxN] (+bias) ----------------
__global__ void __launch_bounds__(256) gemm_bias_kernel(
    const float* __restrict__ A, const float* __restrict__ B,
    const float* __restrict__ bias, float* __restrict__ C,
    int M, int N, int K) {
    __shared__ __align__(16) float As[16][68];
    __shared__ __align__(16) float Bs[16][68];
    const int tid = threadIdx.x;
    const int tx = tid & 15, ty = tid >> 4;
    const int bm = blockIdx.y * 64, bn = blockIdx.x * 64;

    float acc[4][4];
#pragma unroll
    for (int i = 0; i < 4; i++)
#pragma unroll
        for (int j = 0; j < 4; j++) acc[i][j] = 0.f;

    for (int k0 = 0; k0 < K; k0 += 16) {
        {
            int ar = tid >> 2;            // 0..63
            int ac = (tid & 3) * 4;       // 0,4,8,12
            float4 av = *(const float4*)&A[(bm + ar) * K + k0 + ac];
            As[ac + 0][ar] = av.x; As[ac + 1][ar] = av.y;
            As[ac + 2][ar] = av.z; As[ac + 3][ar] = av.w;
        }
        {
            int br = tid >> 4;            // 0..15
            int bc = (tid & 15) * 4;      // 0..60
            *(float4*)&Bs[br][bc] = *(const float4*)&B[(k0 + br) * N + bn + bc];
        }
        __syncthreads();
#pragma unroll
        for (int kk = 0; kk < 16; kk++) {
            float a0 = As[kk][ty * 4 + 0], a1 = As[kk][ty * 4 + 1];
            float a2 = As[kk][ty * 4 + 2], a3 = As[kk][ty * 4 + 3];
            float b0 = Bs[kk][tx * 4 + 0], b1 = Bs[kk][tx * 4 + 1];
            float b2 = Bs[kk][tx * 4 + 2], b3 = Bs[kk][tx * 4 + 3];
            acc[0][0] += a0 * b0; acc[0][1] += a0 * b1; acc[0][2] += a0 * b2; acc[0][3] += a0 * b3;
            acc[1][0] += a1 * b0; acc[1][1] += a1 * b1; acc[1][2] += a1 * b2; acc[1][3] += a1 * b3;
            acc[2][0] += a2 * b0; acc[2][1] += a2 * b1; acc[2][2] += a2 * b2; acc[2][3] += a2 * b3;
            acc[3][0] += a3 * b0; acc[3][1] += a3 * b1; acc[3][2] += a3 * b2; acc[3][3] += a3 * b3;
        }
        __syncthreads();
    }
#pragma unroll
    for (int i = 0; i < 4; i++) {
        int row = bm + ty * 4 + i;
#pragma unroll
        for (int j = 0; j < 4; j++) {
            int col = bn + tx * 4 + j;
            float v = acc[i][j];
            if (bias) v += bias[col];
            C[row * N + col] = v;
        }
    }
}

// ---------------- concat: dst[t, 0:256]=a[t], dst[t, 256:512]=b[t] ----------------
__global__ void concat_kernel(float* __restrict__ dst, const float* __restrict__ a,
                              const float* __restrict__ b) {
    int idx = blockIdx.x * blockDim.x + threadIdx.x;
    int t = idx >> 9;
    int c = idx & 511;
    dst[idx] = (c < LL) ? a[t * LL + c] : b[t * LL + c - LL];
}

// ---------------- persistent dual-direction LSTM phase ----------------
// grid = 2*GPD CTAs, 256 threads. dir 0 = forward, dir 1 = backward (reversed seq).
// Warp w of CTA g owns hidden unit u = g*8 + w; its 4 gate columns are u + gate*256.
// Per step: warp-per-gate dot product (lane covers 8 k's, butterfly reduce),
// ping-pong h buffer in global, generation-based spin barrier per direction.
__global__ void __launch_bounds__(256) lstm_phase_kernel(int layer) {
    const int dir = blockIdx.x >> 5;       // GPD == 32
    const int g   = blockIdx.x & 31;
    const float* xw = (dir == 0) ? g_xw_a : g_xw_b;
    const float* Ut = g_Ut[layer * 2 + dir];
    float* out = (layer == 0) ? ((dir == 0) ? g_rf1 : g_rb1)
                              : ((dir == 0) ? g_rf2 : g_rb2);
    unsigned* cntp = &g_cnt[dir];
    volatile unsigned* genp = &g_gen[dir];

    __shared__ __align__(16) float h_s[LL];
    __shared__ unsigned gen0_s;

    const int tid  = threadIdx.x;
    const int warp = tid >> 5, lane = tid & 31;
    const int u = g * 8 + warp;            // hidden unit owned by this warp
    const int k0 = lane * 8;

    if (tid == 0) gen0_s = *genp;
    __syncthreads();
    const unsigned gen0 = gen0_s;

    const float* w0 = Ut + (0 * LL + u) * LL + k0;
    const float* w1 = Ut + (1 * LL + u) * LL + k0;
    const float* w2 = Ut + (2 * LL + u) * LL + k0;
    const float* w3 = Ut + (3 * LL + u) * LL + k0;

    float c = 0.f;

    for (int s = 0; s < TT; s++) {
        if (s == 0) h_s[tid] = 0.f;
        else        h_s[tid] = g_hbuf[dir][s & 1][tid];
        __syncthreads();

        const int tok = (dir == 0) ? s : (TT - 1 - s);
        float4 hA = *(const float4*)&h_s[k0];
        float4 hB = *(const float4*)&h_s[k0 + 4];

        float z[4];
        const float* wp[4] = {w0, w1, w2, w3};
#pragma unroll
        for (int gt = 0; gt < 4; gt++) {
            float4 a = *(const float4*)(wp[gt]);
            float4 b = *(const float4*)(wp[gt] + 4);
            float acc = a.x * hA.x + a.y * hA.y + a.z * hA.z + a.w * hA.w
                      + b.x * hB.x + b.y * hB.y + b.z * hB.z + b.w * hB.w;
#pragma unroll
            for (int off = 16; off; off >>= 1)
                acc += __shfl_xor_sync(0xffffffffu, acc, off);
            z[gt] = acc + xw[tok * ZDIM + gt * LL + u];
        }

        float iv = fsig(z[0]);
        float fv = fsig(z[1]);
        float gv = ftanh(z[2]);
        float ov = fsig(z[3]);
        c = fv * c + iv * gv;
        float hv = ov * ftanh(c);

        if (lane == 0) {
            g_hbuf[dir][(s + 1) & 1][u] = hv;
            out[tok * LL + u] = hv;
        }

        // ---- inter-CTA barrier (per direction) ----
        __threadfence();
        __syncthreads();
        if (tid == 0) {
            const unsigned target = gen0 + (unsigned)s + 1u;
            unsigned prev = atomicAdd(cntp, 1u);
            if (prev == (unsigned)(GPD - 1)) {
                *cntp = 0u;
                __threadfence();
                *genp = target;
            } else {
                while ((int)(*genp - target) < 0) { }
            }
            __threadfence();
        }
        __syncthreads();
    }
}

// ---------------- pairwise head: out[i,j] = sum_h w[h]*tanh(hf[i,h]+mf[j,h]) + ob ----------------
__global__ void __launch_bounds__(256) pairwise_kernel(
    const float* __restrict__ headf, const float* __restrict__ modf,
    const float* __restrict__ outW, const float* __restrict__ outB,
    float* __restrict__ out) {
    __shared__ __align__(16) float SH[32][132];
    __shared__ float SMt[128][33];
    __shared__ __align__(16) float Wsh[128];

    const int t = threadIdx.x;
    const int i0 = blockIdx.y * 32, j0 = blockIdx.x * 32;
    const int li = t >> 3;
    const int lj = (t & 7) * 4;

    float acc0 = 0.f, acc1 = 0.f, acc2 = 0.f, acc3 = 0.f;

    for (int hc = 0; hc < HH; hc += 128) {
#pragma unroll
        for (int r = 0; r < 4; r++) {
            int idx = t + r * 256;
            int row = idx >> 5;
            int c4 = (idx & 31) * 4;
            float4 hvv = *(const float4*)&headf[(i0 + row) * HH + hc + c4];
            *(float4*)&SH[row][c4] = hvv;
            float4 mvv = *(const float4*)&modf[(j0 + row) * HH + hc + c4];
            SMt[c4 + 0][row] = mvv.x; SMt[c4 + 1][row] = mvv.y;
            SMt[c4 + 2][row] = mvv.z; SMt[c4 + 3][row] = mvv.w;
        }
        if (t < 32) *(float4*)&Wsh[t * 4] = *(const float4*)&outW[hc + t * 4];
        __syncthreads();

#pragma unroll 4
        for (int h = 0; h < 128; h++) {
            float hv = SH[li][h];
            float w = Wsh[h];
            float x0 = hv + SMt[h][lj + 0];
            float x1 = hv + SMt[h][lj + 1];
            float x2 = hv + SMt[h][lj + 2];
            float x3 = hv + SMt[h][lj + 3];
            float e0 = __expf(2.f * x0);
            float e1 = __expf(2.f * x1);
            float e2 = __expf(2.f * x2);
            float e3 = __expf(2.f * x3);
            acc0 += w * (1.f - __fdividef(2.f, e0 + 1.f));
            acc1 += w * (1.f - __fdividef(2.f, e1 + 1.f));
            acc2 += w * (1.f - __fdividef(2.f, e2 + 1.f));
            acc3 += w * (1.f - __fdividef(2.f, e3 + 1.f));
        }
        __syncthreads();
    }

    const float ob = outB[0];
    float* orow = &out[(i0 + li) * TT + j0 + lj];
    orow[0] = acc0 + ob;
    orow[1] = acc1 + ob;
    orow[2] = acc2 + ob;
    orow[3] = acc3 + ob;
}

// ---------------- host side ----------------
extern "C" void kernel_launch(void* const* d_in, const int* in_sizes, int n_in,
                              void* d_out, int out_size) {
    (void)in_sizes; (void)n_in; (void)out_size;
    const float* emb     = (const float*)d_in[0];
    const float* W_f1    = (const float*)d_in[1];
    const float* U_f1    = (const float*)d_in[2];
    const float* b_f1    = (const float*)d_in[3];
    const float* W_b1    = (const float*)d_in[4];
    const float* U_b1    = (const float*)d_in[5];
    const float* b_b1    = (const float*)d_in[6];
    const float* W_f2    = (const float*)d_in[7];
    const float* U_f2    = (const float*)d_in[8];
    const float* b_f2    = (const float*)d_in[9];
    const float* W_b2    = (const float*)d_in[10];
    const float* U_b2    = (const float*)d_in[11];
    const float* b_b2    = (const float*)d_in[12];
    const float* FOH     = (const float*)d_in[13];
    const float* FOM     = (const float*)d_in[14];
    const float* hidBias = (const float*)d_in[15];
    const float* outW    = (const float*)d_in[16];
    const float* outBias = (const float*)d_in[17];

    float *xwa, *xwb, *v, *hcat, *headf, *modf, *rf1, *rb1, *rf2, *rb2;
    cudaGetSymbolAddress((void**)&xwa,   g_xw_a);
    cudaGetSymbolAddress((void**)&xwb,   g_xw_b);
    cudaGetSymbolAddress((void**)&v,     g_v);
    cudaGetSymbolAddress((void**)&hcat,  g_hcat);
    cudaGetSymbolAddress((void**)&headf, g_headf);
    cudaGetSymbolAddress((void**)&modf,  g_modf);
    cudaGetSymbolAddress((void**)&rf1,   g_rf1);
    cudaGetSymbolAddress((void**)&rb1,   g_rb1);
    cudaGetSymbolAddress((void**)&rf2,   g_rf2);
    cudaGetSymbolAddress((void**)&rb2,   g_rb2);

    // 1. transpose all recurrent matrices
    transposeU_kernel<<<dim3(ZDIM / 32, LL / 32, 4), dim3(32, 8)>>>(U_f1, U_b1, U_f2, U_b2);

    // 2. layer-1 input projections (bias folded in)
    gemm_bias_kernel<<<dim3(ZDIM / 64, TT / 64), 256>>>(emb, W_f1, b_f1, xwa, TT, ZDIM, DD);
    gemm_bias_kernel<<<dim3(ZDIM / 64, TT / 64), 256>>>(emb, W_b1, b_b1, xwb, TT, ZDIM, DD);

    // 3. layer-1 BiLSTM (fw + bw concurrently)
    lstm_phase_kernel<<<2 * GPD, 256>>>(0);

    // 4. concat -> v
    concat_kernel<<<(TT * 2 * LL) / 256, 256>>>(v, rf1, rb1);

    // 5. layer-2 input projections
    gemm_bias_kernel<<<dim3(ZDIM / 64, TT / 64), 256>>>(v, W_f2, b_f2, xwa, TT, ZDIM, 2 * LL);
    gemm_bias_kernel<<<dim3(ZDIM / 64, TT / 64), 256>>>(v, W_b2, b_b2, xwb, TT, ZDIM, 2 * LL);

    // 6. layer-2 BiLSTM
    lstm_phase_kernel<<<2 * GPD, 256>>>(1);

    // 7. concat -> hcat
    concat_kernel<<<(TT * 2 * LL) / 256, 256>>>(hcat, rf2, rb2);

    // 8. head projections (hidBias folded into headfov)
    gemm_bias_kernel<<<dim3(HH / 64, TT / 64), 256>>>(hcat, FOH, hidBias, headf, TT, HH, 2 * LL);
    gemm_bias_kernel<<<dim3(HH / 64, TT / 64), 256>>>(hcat, FOM, nullptr,  modf,  TT, HH, 2 * LL);

    // 9. pairwise scores
    pairwise_kernel<<<dim3(TT / 32, TT / 32), 256>>>(headf, modf, outW, outBias, (float*)d_out);
}

// round 2
// speedup vs baseline: 2.8683x; 2.8683x over previous
#include <cuda_runtime.h>
#include <cstdint>

#define TT 512
#define DD 256
#define LL 256
#define HH 512
#define ZDIM 1024
#define CLU 8    // CTAs per cluster = per LSTM direction

// ---------------- device scratch (no allocations allowed) ----------------
__device__ __align__(16) float g_xw_a[TT * ZDIM];
__device__ __align__(16) float g_xw_b[TT * ZDIM];
__device__ __align__(16) float g_Ut[4][ZDIM * LL];   // transposed U: [col = gate*256+u][k]
__device__ __align__(16) float g_v[TT * 2 * LL];     // layer-1 bilstm output (concat layout)
__device__ __align__(16) float g_hcat[TT * 2 * LL];  // layer-2 bilstm output (concat layout)
__device__ __align__(16) float g_headf[TT * HH];
__device__ __align__(16) float g_modf[TT * HH];

// ---------------- fast activations (rel err ~1e-6) ----------------
__device__ __forceinline__ float fsig(float x) {
    float e = __expf(-x);
    return __fdividef(1.f, 1.f + e);
}
__device__ __forceinline__ float ftanh(float x) {
    float e = __expf(2.f * x);
    return 1.f - __fdividef(2.f, e + 1.f);
}

__device__ __forceinline__ uint32_t smem_u32(const void* p) {
    uint32_t a;
    asm("{ .reg .u64 t; cvta.to.shared.u64 t, %1; cvt.u32.u64 %0, t; }" : "=r"(a) : "l"(p));
    return a;
}
__device__ __forceinline__ void cluster_sync_all() {
    asm volatile("barrier.cluster.arrive.aligned;" ::: "memory");
    asm volatile("barrier.cluster.wait.aligned;" ::: "memory");
}

// ---------------- U transpose: [256,1024] -> [1024,256] x4 ----------------
__global__ void transposeU_kernel(const float* __restrict__ u0, const float* __restrict__ u1,
                                  const float* __restrict__ u2, const float* __restrict__ u3) {
    __shared__ float tile[32][33];
    const float* src = (blockIdx.z == 0) ? u0 : (blockIdx.z == 1) ? u1 : (blockIdx.z == 2) ? u2 : u3;
    float* dst = g_Ut[blockIdx.z];
    int j  = blockIdx.x * 32 + threadIdx.x;   // column in U (0..1023)
    int k0 = blockIdx.y * 32;                 // row chunk (0..255)
#pragma unroll
    for (int r = 0; r < 32; r += 8)
        tile[threadIdx.y + r][threadIdx.x] = src[(k0 + threadIdx.y + r) * ZDIM + j];
    __syncthreads();
    int k  = k0 + threadIdx.x;
    int jo = blockIdx.x * 32;
#pragma unroll
    for (int r = 0; r < 32; r += 8)
        dst[(jo + threadIdx.y + r) * LL + k] = tile[threadIdx.x][threadIdx.y + r];
}

// ---------------- dual fp32 tiled GEMM: Cz = A @ Bz (+biasz), z = blockIdx.z ----------------
__global__ void __launch_bounds__(256) gemm2_kernel(
    const float* __restrict__ A0, const float* __restrict__ A1,
    const float* __restrict__ B0, const float* __restrict__ B1,
    const float* __restrict__ bias0, const float* __restrict__ bias1,
    float* __restrict__ C0, float* __restrict__ C1,
    int M, int N, int K) {
    const float* A    = (blockIdx.z == 0) ? A0 : A1;
    const float* B    = (blockIdx.z == 0) ? B0 : B1;
    const float* bias = (blockIdx.z == 0) ? bias0 : bias1;
    float* C          = (blockIdx.z == 0) ? C0 : C1;

    __shared__ __align__(16) float As[16][68];
    __shared__ __align__(16) float Bs[16][68];
    const int tid = threadIdx.x;
    const int tx = tid & 15, ty = tid >> 4;
    const int bm = blockIdx.y * 64, bn = blockIdx.x * 64;

    float acc[4][4];
#pragma unroll
    for (int i = 0; i < 4; i++)
#pragma unroll
        for (int j = 0; j < 4; j++) acc[i][j] = 0.f;

    for (int k0 = 0; k0 < K; k0 += 16) {
        {
            int ar = tid >> 2;            // 0..63
            int ac = (tid & 3) * 4;       // 0,4,8,12
            float4 av = *(const float4*)&A[(bm + ar) * K + k0 + ac];
            As[ac + 0][ar] = av.x; As[ac + 1][ar] = av.y;
            As[ac + 2][ar] = av.z; As[ac + 3][ar] = av.w;
        }
        {
            int br = tid >> 4;            // 0..15
            int bc = (tid & 15) * 4;      // 0..60
            *(float4*)&Bs[br][bc] = *(const float4*)&B[(k0 + br) * N + bn + bc];
        }
        __syncthreads();
#pragma unroll
        for (int kk = 0; kk < 16; kk++) {
            float4 a4 = *(const float4*)&As[kk][ty * 4];
            float4 b4 = *(const float4*)&Bs[kk][tx * 4];
            acc[0][0] += a4.x * b4.x; acc[0][1] += a4.x * b4.y; acc[0][2] += a4.x * b4.z; acc[0][3] += a4.x * b4.w;
            acc[1][0] += a4.y * b4.x; acc[1][1] += a4.y * b4.y; acc[1][2] += a4.y * b4.z; acc[1][3] += a4.y * b4.w;
            acc[2][0] += a4.z * b4.x; acc[2][1] += a4.z * b4.y; acc[2][2] += a4.z * b4.z; acc[2][3] += a4.z * b4.w;
            acc[3][0] += a4.w * b4.x; acc[3][1] += a4.w * b4.y; acc[3][2] += a4.w * b4.z; acc[3][3] += a4.w * b4.w;
        }
        __syncthreads();
    }
#pragma unroll
    for (int i = 0; i < 4; i++) {
        int row = bm + ty * 4 + i;
#pragma unroll
        for (int j = 0; j < 4; j++) {
            int col = bn + tx * 4 + j;
            float v = acc[i][j];
            if (bias) v += bias[col];
            C[row * N + col] = v;
        }
    }
}

// ---------------- cluster LSTM: one 8-CTA cluster per direction ----------------
// grid = 16 CTAs (2 clusters). 256 threads/CTA. U held in registers.
// Warp w, lane: usub = lane>>3 (unit-in-warp), sl = lane&7 (k-slice).
// Unit u = rank*32 + w*4 + usub. Thread covers k in {32j + 4*sl .. +3}, j=0..7.
// h broadcast each step via st.shared::cluster to all 8 CTAs; sync = barrier.cluster.
__global__ void __launch_bounds__(256, 1) __cluster_dims__(CLU, 1, 1)
lstm_cluster_kernel(int layer) {
    const int dir = blockIdx.x / CLU;     // 0 = forward, 1 = backward
    uint32_t rank;
    asm("mov.u32 %0, %%cluster_ctarank;" : "=r"(rank));

    const float* xw = (dir == 0) ? g_xw_a : g_xw_b;
    const float* Ut = g_Ut[layer * 2 + dir];
    float* out = (layer == 0) ? g_v : g_hcat;
    const int coloff = dir * LL;          // concat column offset

    const int tid  = threadIdx.x;
    const int warp = tid >> 5, lane = tid & 31;
    const int usub = lane >> 3, sl = lane & 7;
    const int u = rank * 32 + warp * 4 + usub;

    __shared__ __align__(16) float h_s[2][LL];

    // Load this thread's U slice into registers: 4 gates x 8 float4 = 128 regs
    float4 Ug[4][8];
#pragma unroll
    for (int g = 0; g < 4; g++)
#pragma unroll
        for (int j = 0; j < 8; j++)
            Ug[g][j] = *(const float4*)&Ut[(g * LL + u) * LL + j * 32 + sl * 4];

    // zero initial h
    h_s[0][tid] = 0.f;
    __syncthreads();
    cluster_sync_all();

    const uint32_t ha0 = smem_u32(&h_s[0][u]);
    const uint32_t ha1 = smem_u32(&h_s[1][u]);

    float c = 0.f;

    for (int s = 0; s < TT; s++) {
        const float* hc = h_s[s & 1];
        const int tok = (dir == 0) ? s : (TT - 1 - s);

        // prefetch xw early (L2 resident) — only producing lanes need it
        float xwv0 = 0.f, xwv1 = 0.f, xwv2 = 0.f, xwv3 = 0.f;
        if (sl == 0) {
            const float* xp = &xw[tok * ZDIM + u];
            xwv0 = __ldg(xp + 0 * LL);
            xwv1 = __ldg(xp + 1 * LL);
            xwv2 = __ldg(xp + 2 * LL);
            xwv3 = __ldg(xp + 3 * LL);
        }

        float acc0 = 0.f, acc1 = 0.f, acc2 = 0.f, acc3 = 0.f;
#pragma unroll
        for (int j = 0; j < 8; j++) {
            float4 h4 = *(const float4*)&hc[j * 32 + sl * 4];
            float4 a;
            a = Ug[0][j]; acc0 += a.x * h4.x + a.y * h4.y + a.z * h4.z + a.w * h4.w;
            a = Ug[1][j]; acc1 += a.x * h4.x + a.y * h4.y + a.z * h4.z + a.w * h4.w;
            a = Ug[2][j]; acc2 += a.x * h4.x + a.y * h4.y + a.z * h4.z + a.w * h4.w;
            a = Ug[3][j]; acc3 += a.x * h4.x + a.y * h4.y + a.z * h4.z + a.w * h4.w;
        }
        // reduce across the 8 slices of this unit (lanes usub*8 .. usub*8+7)
#pragma unroll
        for (int off = 4; off; off >>= 1) {
            acc0 += __shfl_down_sync(0xffffffffu, acc0, off, 8);
            acc1 += __shfl_down_sync(0xffffffffu, acc1, off, 8);
            acc2 += __shfl_down_sync(0xffffffffu, acc2, off, 8);
            acc3 += __shfl_down_sync(0xffffffffu, acc3, off, 8);
        }

        if (sl == 0) {
            float iv = fsig(acc0 + xwv0);
            float fv = fsig(acc1 + xwv1);
            float gv = ftanh(acc2 + xwv2);
            float ov = fsig(acc3 + xwv3);
            c = fv * c + iv * gv;
            float hv = ov * ftanh(c);

            out[tok * (2 * LL) + coloff + u] = hv;

            // broadcast h to next-step buffer in all 8 cluster CTAs
            uint32_t base = ((s & 1) == 0) ? ha1 : ha0;
#pragma unroll
            for (int r = 0; r < CLU; r++) {
                uint32_t dst;
                asm("mapa.shared::cluster.u32 %0, %1, %2;" : "=r"(dst) : "r"(base), "r"(r));
                asm volatile("st.shared::cluster.f32 [%0], %1;" :: "r"(dst), "f"(hv) : "memory");
            }
        }
        cluster_sync_all();   // release/acquire: orders the remote h stores
    }
}

// ---------------- pairwise head: out[i,j] = sum_h w[h]*tanh(hf[i,h]+mf[j,h]) + ob ----------------
__global__ void __launch_bounds__(256) pairwise_kernel(
    const float* __restrict__ headf, const float* __restrict__ modf,
    const float* __restrict__ outW, const float* __restrict__ outB,
    float* __restrict__ out) {
    __shared__ __align__(16) float SH[32][132];
    __shared__ float SMt[128][33];
    __shared__ __align__(16) float Wsh[128];

    const int t = threadIdx.x;
    const int i0 = blockIdx.y * 32, j0 = blockIdx.x * 32;
    const int li = t >> 3;
    const int lj = (t & 7) * 4;

    float acc0 = 0.f, acc1 = 0.f, acc2 = 0.f, acc3 = 0.f;

    for (int hc = 0; hc < HH; hc += 128) {
#pragma unroll
        for (int r = 0; r < 4; r++) {
            int idx = t + r * 256;
            int row = idx >> 5;
            int c4 = (idx & 31) * 4;
            float4 hvv = *(const float4*)&headf[(i0 + row) * HH + hc + c4];
            *(float4*)&SH[row][c4] = hvv;
            float4 mvv = *(const float4*)&modf[(j0 + row) * HH + hc + c4];
            SMt[c4 + 0][row] = mvv.x; SMt[c4 + 1][row] = mvv.y;
            SMt[c4 + 2][row] = mvv.z; SMt[c4 + 3][row] = mvv.w;
        }
        if (t < 32) *(float4*)&Wsh[t * 4] = *(const float4*)&outW[hc + t * 4];
        __syncthreads();

#pragma unroll 4
        for (int h = 0; h < 128; h++) {
            float hv = SH[li][h];
            float w = Wsh[h];
            float x0 = hv + SMt[h][lj + 0];
            float x1 = hv + SMt[h][lj + 1];
            float x2 = hv + SMt[h][lj + 2];
            float x3 = hv + SMt[h][lj + 3];
            float e0 = __expf(2.f * x0);
            float e1 = __expf(2.f * x1);
            float e2 = __expf(2.f * x2);
            float e3 = __expf(2.f * x3);
            acc0 += w * (1.f - __fdividef(2.f, e0 + 1.f));
            acc1 += w * (1.f - __fdividef(2.f, e1 + 1.f));
            acc2 += w * (1.f - __fdividef(2.f, e2 + 1.f));
            acc3 += w * (1.f - __fdividef(2.f, e3 + 1.f));
        }
        __syncthreads();
    }

    const float ob = outB[0];
    float* orow = &out[(i0 + li) * TT + j0 + lj];
    orow[0] = acc0 + ob;
    orow[1] = acc1 + ob;
    orow[2] = acc2 + ob;
    orow[3] = acc3 + ob;
}

// ---------------- host side ----------------
extern "C" void kernel_launch(void* const* d_in, const int* in_sizes, int n_in,
                              void* d_out, int out_size) {
    (void)in_sizes; (void)n_in; (void)out_size;
    const float* emb     = (const float*)d_in[0];
    const float* W_f1    = (const float*)d_in[1];
    const float* U_f1    = (const float*)d_in[2];
    const float* b_f1    = (const float*)d_in[3];
    const float* W_b1    = (const float*)d_in[4];
    const float* U_b1    = (const float*)d_in[5];
    const float* b_b1    = (const float*)d_in[6];
    const float* W_f2    = (const float*)d_in[7];
    const float* U_f2    = (const float*)d_in[8];
    const float* b_f2    = (const float*)d_in[9];
    const float* W_b2    = (const float*)d_in[10];
    const float* U_b2    = (const float*)d_in[11];
    const float* b_b2    = (const float*)d_in[12];
    const float* FOH     = (const float*)d_in[13];
    const float* FOM     = (const float*)d_in[14];
    const float* hidBias = (const float*)d_in[15];
    const float* outW    = (const float*)d_in[16];
    const float* outBias = (const float*)d_in[17];

    float *xwa, *xwb, *v, *hcat, *headf, *modf;
    cudaGetSymbolAddress((void**)&xwa,   g_xw_a);
    cudaGetSymbolAddress((void**)&xwb,   g_xw_b);
    cudaGetSymbolAddress((void**)&v,     g_v);
    cudaGetSymbolAddress((void**)&hcat,  g_hcat);
    cudaGetSymbolAddress((void**)&headf, g_headf);
    cudaGetSymbolAddress((void**)&modf,  g_modf);

    // 1. transpose all recurrent matrices
    transposeU_kernel<<<dim3(ZDIM / 32, LL / 32, 4), dim3(32, 8)>>>(U_f1, U_b1, U_f2, U_b2);

    // 2. layer-1 input projections (both directions, bias folded in)
    gemm2_kernel<<<dim3(ZDIM / 64, TT / 64, 2), 256>>>(
        emb, emb, W_f1, W_b1, b_f1, b_b1, xwa, xwb, TT, ZDIM, DD);

    // 3. layer-1 BiLSTM (fw + bw clusters concurrently), writes concat layout -> v
    lstm_cluster_kernel<<<2 * CLU, 256>>>(0);

    // 4. layer-2 input projections
    gemm2_kernel<<<dim3(ZDIM / 64, TT / 64, 2), 256>>>(
        v, v, W_f2, W_b2, b_f2, b_b2, xwa, xwb, TT, ZDIM, 2 * LL);

    // 5. layer-2 BiLSTM -> hcat
    lstm_cluster_kernel<<<2 * CLU, 256>>>(1);

    // 6. head projections (hidBias folded into headfov)
    gemm2_kernel<<<dim3(HH / 64, TT / 64, 2), 256>>>(
        hcat, hcat, FOH, FOM, hidBias, nullptr, headf, modf, TT, HH, 2 * LL);

    // 7. pairwise scores
    pairwise_kernel<<<dim3(TT / 32, TT / 32), 256>>>(headf, modf, outW, outBias, (float*)d_out);
}